// round 15
// baseline (speedup 1.0000x reference)
#include <cuda_runtime.h>
#include <math.h>

#define B    16
#define IN   1024
#define HH   1024
#define DKK  1024
#define D1   4096
#define LRC  0.01f
#define NCH  64
#define CI   16

// ---------------- scratch (allocation-free) ----------------
__device__ __align__(16) float g_K  [B * DKK];          // b-major
__device__ __align__(16) float g_V  [B * HH];           // b-major
__device__ __align__(16) float g_G  [B * D1];           // b-major
__device__ __align__(16) float g_Gp [B * D1];           // b-major
__device__ __align__(16) float g_Hd [B * HH];           // b-major
__device__ __align__(16) float g_dHt[HH * B];           // i-major
__device__ __align__(16) float g_part[NCH * B * D1];    // [c][b][j], 16 MB
// g_sync: [0]=proj, [1]=zgelu, [2]=hdh, [3..6]=w1 quadrants
__device__ unsigned g_sync[8];

__global__ void reset_kernel() {
#pragma unroll
    for (int i = 0; i < 8; i++) g_sync[i] = 0u;
}

__device__ __forceinline__ void wait_cnt(unsigned idx, unsigned target, int tid) {
    if (tid == 0) {
        volatile unsigned* p = &g_sync[idx];
        while (*p < target) __nanosleep(32);
    }
    __syncthreads();
    __threadfence();
}
__device__ __forceinline__ void signal_cnt(unsigned idx, int tid) {
    __threadfence();
    __syncthreads();
    if (tid == 0) atomicAdd(&g_sync[idx], 1u);
}

__device__ __forceinline__ float warp_sum(float v) {
    v += __shfl_xor_sync(0xffffffffu, v, 16);
    v += __shfl_xor_sync(0xffffffffu, v, 8);
    v += __shfl_xor_sync(0xffffffffu, v, 4);
    v += __shfl_xor_sync(0xffffffffu, v, 2);
    v += __shfl_xor_sync(0xffffffffu, v, 1);
    return v;
}
__device__ __forceinline__ float dot4(float4 a, float4 b) {
    return a.x * b.x + a.y * b.y + a.z * b.z + a.w * b.w;
}

// ================= MEGA WAVE: 1280 blocks, in-order dispatch = dependency order =================
// [0,128)     proj (K+V)
// [128,384)   zgelu        (waits proj==128)
// [384,512)   hdh          (waits zgelu==256)
// [512,768)   w1 update + dG partials (waits hdh==128) -> signals quad jt
// [768,1024)  out GEMV     (waits hdh==128)
// [1024,1280) dZ reduce + w0 update (waits w1 quad==64)
__global__ void mega_wave_kernel(const float* __restrict__ X,
                                 const float* __restrict__ Wk,
                                 const float* __restrict__ Wv,
                                 const float* __restrict__ Wo,
                                 const float* __restrict__ W0,
                                 const float* __restrict__ W1,
                                 float* __restrict__ out,
                                 float* __restrict__ out_w0,
                                 float* __restrict__ out_w1) {
    __shared__ float smem[512];
    int tid  = threadIdx.x;
    int w    = tid >> 5, lane = tid & 31;
    int bx   = blockIdx.x;

    if (bx < 128) {
        // ---------------- proj ----------------
        int rgl = w >> 1, half = w & 1;
        int rg = bx * 4 + rgl;                    // 0..511
        const float* Wb = (rg >> 8) ? Wv : Wk;
        int row0 = (rg * 4) & 1023;
        int ibase = half * 512;
        const float* wp = Wb + (size_t)row0 * IN + ibase;
        const float* xp = X + ibase;

        float acc[4][16];
#pragma unroll
        for (int r = 0; r < 4; r++)
#pragma unroll
            for (int b = 0; b < 16; b++) acc[r][b] = 0.f;
#pragma unroll
        for (int it = 0; it < 4; it++) {
            int i = it * 128 + lane * 4;
            float4 wv[4];
#pragma unroll
            for (int r = 0; r < 4; r++) wv[r] = __ldg((const float4*)(wp + r * IN + i));
#pragma unroll
            for (int b = 0; b < 16; b++) {
                float4 x4 = __ldg((const float4*)(xp + b * IN + i));
#pragma unroll
                for (int r = 0; r < 4; r++) acc[r][b] += dot4(wv[r], x4);
            }
        }
#pragma unroll
        for (int r = 0; r < 4; r++)
#pragma unroll
            for (int b = 0; b < 16; b++) acc[r][b] = warp_sum(acc[r][b]);
        if (lane == 0) {
#pragma unroll
            for (int r = 0; r < 4; r++)
#pragma unroll
                for (int b = 0; b < 16; b++)
                    smem[rgl * 128 + half * 64 + r * 16 + b] = acc[r][b];
        }
        __syncthreads();
        {
            int rg2 = tid >> 6, r = (tid >> 4) & 3, b = tid & 15;
            float v = smem[rg2 * 128 + r * 16 + b] + smem[rg2 * 128 + 64 + r * 16 + b];
            int row = (bx * 4 + rg2) * 4 + r;
            float* o = (row >> 10) ? g_V : g_K;
            o[b * 1024 + (row & 1023)] = v;
        }
        signal_cnt(0, tid);
    } else if (bx < 384) {
        // ---------------- zgelu ----------------
        wait_cnt(0, 128, tid);
        int bz = bx - 128;                        // 0..255
        int rgl = w >> 1, half = w & 1;
        int rg = bz * 4 + rgl;                    // 0..1023
        int j0 = rg * 4;
        int ibase = half * 512;
        const float* wp = W0 + (size_t)j0 * DKK + ibase;

        float acc[4][16];
#pragma unroll
        for (int r = 0; r < 4; r++)
#pragma unroll
            for (int b = 0; b < 16; b++) acc[r][b] = 0.f;
#pragma unroll
        for (int it = 0; it < 4; it++) {
            int i = it * 128 + lane * 4;
            float4 wv[4];
#pragma unroll
            for (int r = 0; r < 4; r++) wv[r] = __ldg((const float4*)(wp + r * DKK + i));
#pragma unroll
            for (int b = 0; b < 16; b++) {
                float4 k4 = *(const float4*)(g_K + b * DKK + ibase + i);
#pragma unroll
                for (int r = 0; r < 4; r++) acc[r][b] += dot4(wv[r], k4);
            }
        }
#pragma unroll
        for (int r = 0; r < 4; r++)
#pragma unroll
            for (int b = 0; b < 16; b++) acc[r][b] = warp_sum(acc[r][b]);
        if (lane == 0) {
#pragma unroll
            for (int r = 0; r < 4; r++)
#pragma unroll
                for (int b = 0; b < 16; b++)
                    smem[rgl * 128 + half * 64 + r * 16 + b] = acc[r][b];
        }
        __syncthreads();
        {
            int rg2 = tid >> 6, r = (tid >> 4) & 3, b = tid & 15;
            float z = smem[rg2 * 128 + r * 16 + b] + smem[rg2 * 128 + 64 + r * 16 + b];
            int j = (bz * 4 + rg2) * 4 + r;
            float c  = 0.5f * (1.f + erff(z * 0.70710678118654752f));
            float g  = z * c;
            float gp = c + z * 0.39894228040143268f * expf(-0.5f * z * z);
            g_G [b * D1 + j] = g;
            g_Gp[b * D1 + j] = gp;
        }
        signal_cnt(1, tid);
    } else if (bx < 512) {
        // ---------------- hdh ----------------
        wait_cnt(1, 256, tid);
        int bh = bx - 384;                        // 0..127
        int rgl = w >> 2, s = w & 3;
        int rg = bh * 2 + rgl;                    // 0..255
        int i0 = rg * 4;
        int jbase = s * 1024;
        const float* wp = W1 + (size_t)i0 * D1 + jbase;

        float acc[4][16];
#pragma unroll
        for (int r = 0; r < 4; r++)
#pragma unroll
            for (int b = 0; b < 16; b++) acc[r][b] = 0.f;
#pragma unroll
        for (int it = 0; it < 8; it++) {
            int j = it * 128 + lane * 4;
            float4 wv[4];
#pragma unroll
            for (int r = 0; r < 4; r++) wv[r] = __ldg((const float4*)(wp + r * D1 + j));
#pragma unroll
            for (int b = 0; b < 16; b++) {
                float4 g4 = *(const float4*)(g_G + b * D1 + jbase + j);
#pragma unroll
                for (int r = 0; r < 4; r++) acc[r][b] += dot4(wv[r], g4);
            }
        }
#pragma unroll
        for (int r = 0; r < 4; r++)
#pragma unroll
            for (int b = 0; b < 16; b++) acc[r][b] = warp_sum(acc[r][b]);
        if (lane == 0) {
#pragma unroll
            for (int r = 0; r < 4; r++)
#pragma unroll
                for (int b = 0; b < 16; b++)
                    smem[rgl * 256 + s * 64 + r * 16 + b] = acc[r][b];
        }
        __syncthreads();
        if (tid < 128) {
            int rg2 = tid >> 6, r = (tid >> 4) & 3, b = tid & 15;
            float h = smem[rg2 * 256 + 0 * 64 + r * 16 + b] + smem[rg2 * 256 + 1 * 64 + r * 16 + b]
                    + smem[rg2 * 256 + 2 * 64 + r * 16 + b] + smem[rg2 * 256 + 3 * 64 + r * 16 + b];
            int i = (bh * 2 + rg2) * 4 + r;
            g_Hd [b * HH + i] = h;
            g_dHt[i * B + b]  = (h - g_V[b * HH + i]) * (1.0f / (float)HH);
        }
        signal_cnt(2, tid);
    } else if (bx < 768) {
        // ---------------- w1 update + partials ----------------
        wait_cnt(2, 128, tid);
        float* sdh = smem;                        // [CI*B]
        int bw = bx - 512;                        // 0..255
        int c  = bw >> 2;
        int jt = bw & 3;
        int i0 = c * CI;
        int j  = jt * 1024 + tid * 4;

        sdh[tid] = g_dHt[i0 * B + tid];
        __syncthreads();

#pragma unroll
        for (int half = 0; half < 2; half++) {
            float4 gg[8], acc[8];
#pragma unroll
            for (int bb = 0; bb < 8; bb++) {
                gg[bb]  = *(const float4*)(g_G + (half * 8 + bb) * D1 + j);
                acc[bb] = make_float4(0.f, 0.f, 0.f, 0.f);
            }
#pragma unroll 4
            for (int r = 0; r < CI; r++) {
                int i = i0 + r;
                float4 w4 = __ldg((const float4*)(W1 + (size_t)i * D1 + j));
                float* dst = out_w1 + (size_t)i * D1 + j;
#pragma unroll
                for (int bb = 0; bb < 8; bb++) {
                    int b = half * 8 + bb;
                    float dh = sdh[r * B + b];
                    acc[bb].x += dh * w4.x;
                    acc[bb].y += dh * w4.y;
                    acc[bb].z += dh * w4.z;
                    acc[bb].w += dh * w4.w;
                    float t = LRC * dh;
                    float4 o;
                    o.x = w4.x - t * gg[bb].x;
                    o.y = w4.y - t * gg[bb].y;
                    o.z = w4.z - t * gg[bb].z;
                    o.w = w4.w - t * gg[bb].w;
                    __stcs((float4*)(dst + (size_t)b * HH * D1), o);
                }
            }
#pragma unroll
            for (int bb = 0; bb < 8; bb++)
                *(float4*)(g_part + ((size_t)c * B + half * 8 + bb) * D1 + j) = acc[bb];
        }
        signal_cnt(3 + jt, tid);
    } else if (bx < 1024) {
        // ---------------- out GEMV ----------------
        wait_cnt(2, 128, tid);
        int bx2  = bx - 768;
        int r = w >> 1;
        int s = w & 1;
        int n = bx2 * 4 + r;
        const float* wrow = Wo + (size_t)n * HH + s * 512;

        float acc[B];
#pragma unroll
        for (int b = 0; b < B; b++) acc[b] = 0.f;
#pragma unroll 4
        for (int it = 0; it < 4; it++) {
            int h0 = it * 128 + lane * 4;
            float4 w4 = __ldg((const float4*)(wrow + h0));
#pragma unroll
            for (int b = 0; b < B; b++) {
                float4 h4 = *(const float4*)(g_Hd + b * HH + s * 512 + h0);
                acc[b] += dot4(w4, h4);
            }
        }
#pragma unroll
        for (int b = 0; b < B; b++) acc[b] = warp_sum(acc[b]);
        if (lane == 0) {
#pragma unroll
            for (int b = 0; b < B; b++) smem[r * 32 + s * 16 + b] = acc[b];
        }
        __syncthreads();
        if (tid < 64) {
            int rr = tid >> 4;
            int b  = tid & 15;
            int nn = bx2 * 4 + rr;
            out[b * IN + nn] = smem[rr * 32 + b] + smem[rr * 32 + 16 + b];
        }
    } else {
        // ---------------- dZ reduce + w0 update ----------------
        float* sdz = smem;                        // [256]
        int q    = bx - 1024;                     // 0..255
        int d1_0 = q * 16;
        int quad = q >> 6;
        wait_cnt(3 + quad, 64, tid);

        {
            int b = tid >> 4, d = tid & 15;
            const float* pp = g_part + (size_t)b * D1 + d1_0 + d;
            float s = 0.f;
#pragma unroll 16
            for (int c = 0; c < NCH; c++)
                s += __ldcg(pp + (size_t)c * (B * D1));
            sdz[b * 16 + d] = LRC * s * g_Gp[b * D1 + d1_0 + d];
        }
        __syncthreads();

        int col = tid * 4;
        float4 kk[16];
#pragma unroll
        for (int b = 0; b < 16; b++) kk[b] = *(const float4*)(g_K + b * DKK + col);

#pragma unroll 2
        for (int r = 0; r < 16; r++) {
            int d1 = d1_0 + r;
            float4 w4 = __ldg((const float4*)(W0 + (size_t)d1 * DKK + col));
#pragma unroll
            for (int b = 0; b < 16; b++) {
                float s = sdz[b * 16 + r];
                float4 o;
                o.x = w4.x - s * kk[b].x;
                o.y = w4.y - s * kk[b].y;
                o.z = w4.z - s * kk[b].z;
                o.w = w4.w - s * kk[b].w;
                __stcs((float4*)(out_w0 + ((size_t)b * D1 + d1) * DKK + col), o);
            }
        }
    }
}

extern "C" void kernel_launch(void* const* d_in, const int* in_sizes, int n_in,
                              void* d_out, int out_size) {
    const float* x  = (const float*)d_in[0];
    const float* Wk = (const float*)d_in[1];
    const float* Wv = (const float*)d_in[2];
    const float* Wo = (const float*)d_in[3];
    const float* W0 = (const float*)d_in[4];
    const float* W1 = (const float*)d_in[5];

    float* out    = (float*)d_out;
    float* out_w0 = out + (size_t)B * IN;
    float* out_w1 = out_w0 + (size_t)B * D1 * DKK;

    reset_kernel   <<<1, 1>>>();
    mega_wave_kernel<<<1280, 256>>>(x, Wk, Wv, Wo, W0, W1, out, out_w0, out_w1);
}

// round 16
// speedup vs baseline: 1.2030x; 1.2030x over previous
#include <cuda_runtime.h>
#include <math.h>

#define B    16
#define IN   1024
#define HH   1024
#define DKK  1024
#define D1   4096
#define LRC  0.01f
#define NCH  64
#define CI   16

// ---------------- scratch (allocation-free) ----------------
__device__ __align__(16) float g_K  [B * DKK];          // b-major
__device__ __align__(16) float g_V  [B * HH];           // b-major
__device__ __align__(16) float g_G  [B * D1];           // b-major
__device__ __align__(16) float g_Gp [B * D1];           // b-major
__device__ __align__(16) float g_Hd [B * HH];           // b-major
__device__ __align__(16) float g_dHt[HH * B];           // i-major
__device__ __align__(16) float g_part[NCH * B * D1];    // [c][b][j], 16 MB

__device__ __forceinline__ float warp_sum(float v) {
    v += __shfl_xor_sync(0xffffffffu, v, 16);
    v += __shfl_xor_sync(0xffffffffu, v, 8);
    v += __shfl_xor_sync(0xffffffffu, v, 4);
    v += __shfl_xor_sync(0xffffffffu, v, 2);
    v += __shfl_xor_sync(0xffffffffu, v, 1);
    return v;
}
__device__ __forceinline__ float dot4(float4 a, float4 b) {
    return a.x * b.x + a.y * b.y + a.z * b.z + a.w * b.w;
}

// ---------------- proj: rows 0..1023 -> K, 1024..2047 -> V ----------------
__global__ void __launch_bounds__(256, 2)
proj_kernel(const float* __restrict__ X,
            const float* __restrict__ Wk,
            const float* __restrict__ Wv) {
    __shared__ float sm[4][2][64];
    int w = threadIdx.x >> 5, lane = threadIdx.x & 31;
    int rgl = w >> 1, half = w & 1;
    int rg = blockIdx.x * 4 + rgl;            // 0..511
    const float* Wb = (rg >> 8) ? Wv : Wk;
    int row0 = (rg * 4) & 1023;
    int ibase = half * 512;
    const float* wp = Wb + (size_t)row0 * IN + ibase;
    const float* xp = X + ibase;

    float acc[4][16];
#pragma unroll
    for (int r = 0; r < 4; r++)
#pragma unroll
        for (int b = 0; b < 16; b++) acc[r][b] = 0.f;

#pragma unroll
    for (int it = 0; it < 4; it++) {
        int i = it * 128 + lane * 4;
        float4 wv[4];
#pragma unroll
        for (int r = 0; r < 4; r++) wv[r] = __ldg((const float4*)(wp + r * IN + i));
#pragma unroll
        for (int b = 0; b < 16; b++) {
            float4 x4 = __ldg((const float4*)(xp + b * IN + i));
#pragma unroll
            for (int r = 0; r < 4; r++) acc[r][b] += dot4(wv[r], x4);
        }
    }
#pragma unroll
    for (int r = 0; r < 4; r++)
#pragma unroll
        for (int b = 0; b < 16; b++) acc[r][b] = warp_sum(acc[r][b]);
    if (lane == 0) {
#pragma unroll
        for (int r = 0; r < 4; r++)
#pragma unroll
            for (int b = 0; b < 16; b++) sm[rgl][half][r * 16 + b] = acc[r][b];
    }
    __syncthreads();
    {
        int t = threadIdx.x;
        int rg2 = t >> 6, r = (t >> 4) & 3, b = t & 15;
        float v = sm[rg2][0][r * 16 + b] + sm[rg2][1][r * 16 + b];
        int row = (blockIdx.x * 4 + rg2) * 4 + r;
        float* o = (row >> 10) ? g_V : g_K;
        o[b * 1024 + (row & 1023)] = v;
    }
}

// ---------------- zgelu: Z = K @ W0^T ; G, Gp ----------------
__global__ void __launch_bounds__(256, 2)
zgelu_kernel(const float* __restrict__ W0) {
    __shared__ float sm[4][2][64];
    int w = threadIdx.x >> 5, lane = threadIdx.x & 31;
    int rgl = w >> 1, half = w & 1;
    int rg = blockIdx.x * 4 + rgl;            // 0..1023
    int j0 = rg * 4;
    int ibase = half * 512;
    const float* wp = W0 + (size_t)j0 * DKK + ibase;

    float acc[4][16];
#pragma unroll
    for (int r = 0; r < 4; r++)
#pragma unroll
        for (int b = 0; b < 16; b++) acc[r][b] = 0.f;

#pragma unroll
    for (int it = 0; it < 4; it++) {
        int i = it * 128 + lane * 4;
        float4 wv[4];
#pragma unroll
        for (int r = 0; r < 4; r++) wv[r] = __ldg((const float4*)(wp + r * DKK + i));
#pragma unroll
        for (int b = 0; b < 16; b++) {
            float4 k4 = *(const float4*)(g_K + b * DKK + ibase + i);
#pragma unroll
            for (int r = 0; r < 4; r++) acc[r][b] += dot4(wv[r], k4);
        }
    }
#pragma unroll
    for (int r = 0; r < 4; r++)
#pragma unroll
        for (int b = 0; b < 16; b++) acc[r][b] = warp_sum(acc[r][b]);
    if (lane == 0) {
#pragma unroll
        for (int r = 0; r < 4; r++)
#pragma unroll
            for (int b = 0; b < 16; b++) sm[rgl][half][r * 16 + b] = acc[r][b];
    }
    __syncthreads();
    {
        int t = threadIdx.x;
        int rg2 = t >> 6, r = (t >> 4) & 3, b = t & 15;
        float z = sm[rg2][0][r * 16 + b] + sm[rg2][1][r * 16 + b];
        int j = (blockIdx.x * 4 + rg2) * 4 + r;
        float c  = 0.5f * (1.f + erff(z * 0.70710678118654752f));
        float g  = z * c;
        float gp = c + z * 0.39894228040143268f * expf(-0.5f * z * z);
        g_G [b * D1 + j] = g;
        g_Gp[b * D1 + j] = gp;
    }
}

// ---------------- hdh: Hd = G @ W1^T ; dH ----------------
__global__ void __launch_bounds__(256, 2)
hdh_kernel(const float* __restrict__ W1) {
    __shared__ float sm[2][4][64];
    int w = threadIdx.x >> 5, lane = threadIdx.x & 31;
    int rgl = w >> 2, s = w & 3;
    int rg = blockIdx.x * 2 + rgl;            // 0..255
    int i0 = rg * 4;
    int jbase = s * 1024;
    const float* wp = W1 + (size_t)i0 * D1 + jbase;

    float acc[4][16];
#pragma unroll
    for (int r = 0; r < 4; r++)
#pragma unroll
        for (int b = 0; b < 16; b++) acc[r][b] = 0.f;

#pragma unroll
    for (int it = 0; it < 8; it++) {
        int j = it * 128 + lane * 4;
        float4 wv[4];
#pragma unroll
        for (int r = 0; r < 4; r++) wv[r] = __ldg((const float4*)(wp + r * D1 + j));
#pragma unroll
        for (int b = 0; b < 16; b++) {
            float4 g4 = *(const float4*)(g_G + b * D1 + jbase + j);
#pragma unroll
            for (int r = 0; r < 4; r++) acc[r][b] += dot4(wv[r], g4);
        }
    }
#pragma unroll
    for (int r = 0; r < 4; r++)
#pragma unroll
        for (int b = 0; b < 16; b++) acc[r][b] = warp_sum(acc[r][b]);
    if (lane == 0) {
#pragma unroll
        for (int r = 0; r < 4; r++)
#pragma unroll
            for (int b = 0; b < 16; b++) sm[rgl][s][r * 16 + b] = acc[r][b];
    }
    __syncthreads();
    if (threadIdx.x < 128) {
        int t = threadIdx.x;
        int rg2 = t >> 6, r = (t >> 4) & 3, b = t & 15;
        float h = sm[rg2][0][r * 16 + b] + sm[rg2][1][r * 16 + b]
                + sm[rg2][2][r * 16 + b] + sm[rg2][3][r * 16 + b];
        int i = (blockIdx.x * 2 + rg2) * 4 + r;
        g_Hd [b * HH + i] = h;
        g_dHt[i * B + b]  = (h - g_V[b * HH + i]) * (1.0f / (float)HH);
    }
}

// ---------------- MEGA: W1 update + dG partials (blocks 0..255) | output GEMV (256..511) ----------------
__global__ void fused_w1_out_kernel(const float* __restrict__ W1,
                                    const float* __restrict__ Wo,
                                    float* __restrict__ out_w1,
                                    float* __restrict__ out) {
    int tid = threadIdx.x;
    if (blockIdx.x < 256) {
        __shared__ float sdh[CI * B];
        int c  = blockIdx.x >> 2;           // 0..63
        int jt = blockIdx.x & 3;
        int i0 = c * CI;
        int j  = jt * 1024 + tid * 4;

        sdh[tid] = g_dHt[i0 * B + tid];     // 16 rows x 16 b
        __syncthreads();

#pragma unroll
        for (int half = 0; half < 2; half++) {
            float4 gg[8], acc[8];
#pragma unroll
            for (int bb = 0; bb < 8; bb++) {
                gg[bb]  = *(const float4*)(g_G + (half * 8 + bb) * D1 + j);
                acc[bb] = make_float4(0.f, 0.f, 0.f, 0.f);
            }
#pragma unroll 4
            for (int r = 0; r < CI; r++) {
                int i = i0 + r;
                float4 w4 = __ldg((const float4*)(W1 + (size_t)i * D1 + j));
                float* dst = out_w1 + (size_t)i * D1 + j;
#pragma unroll
                for (int bb = 0; bb < 8; bb++) {
                    int b = half * 8 + bb;
                    float dh = sdh[r * B + b];
                    acc[bb].x += dh * w4.x;
                    acc[bb].y += dh * w4.y;
                    acc[bb].z += dh * w4.z;
                    acc[bb].w += dh * w4.w;
                    float t = LRC * dh;
                    float4 o;
                    o.x = w4.x - t * gg[bb].x;
                    o.y = w4.y - t * gg[bb].y;
                    o.z = w4.z - t * gg[bb].z;
                    o.w = w4.w - t * gg[bb].w;
                    __stcs((float4*)(dst + (size_t)b * HH * D1), o);
                }
            }
#pragma unroll
            for (int bb = 0; bb < 8; bb++)
                *(float4*)(g_part + ((size_t)c * B + half * 8 + bb) * D1 + j) = acc[bb];
        }
    } else {
        // output = Hd @ Wo^T (split-2, 4 rows/block)
        __shared__ float sm[4][2][B];
        int bx2  = blockIdx.x - 256;
        int w    = tid >> 5;
        int lane = tid & 31;
        int r = w >> 1;
        int s = w & 1;
        int n = bx2 * 4 + r;
        const float* wrow = Wo + (size_t)n * HH + s * 512;

        float acc[B];
#pragma unroll
        for (int b = 0; b < B; b++) acc[b] = 0.f;

#pragma unroll 4
        for (int it = 0; it < 4; it++) {
            int h0 = it * 128 + lane * 4;
            float4 w4 = __ldg((const float4*)(wrow + h0));
#pragma unroll
            for (int b = 0; b < B; b++) {
                float4 h4 = *(const float4*)(g_Hd + b * HH + s * 512 + h0);
                acc[b] += dot4(w4, h4);
            }
        }
#pragma unroll
        for (int b = 0; b < B; b++) acc[b] = warp_sum(acc[b]);
        if (lane == 0) {
#pragma unroll
            for (int b = 0; b < B; b++) sm[r][s][b] = acc[b];
        }
        __syncthreads();
        if (tid < 64) {
            int rr = tid >> 4;
            int b  = tid & 15;
            int nn = bx2 * 4 + rr;
            out[b * IN + nn] = sm[rr][0][b] + sm[rr][1][b];
        }
    }
}

// ---------------- fused: dZ reduce + W0 update. 256 blocks x 256 thr, 16 d1-rows each ----------------
__global__ void fused_w0_kernel(const float* __restrict__ W0,
                                float* __restrict__ out_w0) {
    __shared__ float sdz[256];                 // [b][r]
    int tid  = threadIdx.x;
    int d1_0 = blockIdx.x * 16;

    {
        int b = tid >> 4, d = tid & 15;
        const float* pp = g_part + (size_t)b * D1 + d1_0 + d;
        float s = 0.f;
#pragma unroll 16
        for (int c = 0; c < NCH; c++)
            s += pp[(size_t)c * (B * D1)];
        sdz[b * 16 + d] = LRC * s * g_Gp[b * D1 + d1_0 + d];
    }
    __syncthreads();

    int col = tid * 4;
    float4 kk[16];
#pragma unroll
    for (int b = 0; b < 16; b++) kk[b] = *(const float4*)(g_K + b * DKK + col);

#pragma unroll 2
    for (int r = 0; r < 16; r++) {
        int d1 = d1_0 + r;
        float4 w4 = __ldg((const float4*)(W0 + (size_t)d1 * DKK + col));
#pragma unroll
        for (int b = 0; b < 16; b++) {
            float s = sdz[b * 16 + r];
            float4 o;
            o.x = w4.x - s * kk[b].x;
            o.y = w4.y - s * kk[b].y;
            o.z = w4.z - s * kk[b].z;
            o.w = w4.w - s * kk[b].w;
            __stcs((float4*)(out_w0 + ((size_t)b * D1 + d1) * DKK + col), o);
        }
    }
}

extern "C" void kernel_launch(void* const* d_in, const int* in_sizes, int n_in,
                              void* d_out, int out_size) {
    const float* x  = (const float*)d_in[0];
    const float* Wk = (const float*)d_in[1];
    const float* Wv = (const float*)d_in[2];
    const float* Wo = (const float*)d_in[3];
    const float* W0 = (const float*)d_in[4];
    const float* W1 = (const float*)d_in[5];

    float* out    = (float*)d_out;
    float* out_w0 = out + (size_t)B * IN;
    float* out_w1 = out_w0 + (size_t)B * D1 * DKK;

    proj_kernel        <<<128, 256>>>(x, Wk, Wv);
    zgelu_kernel       <<<256, 256>>>(W0);
    hdh_kernel         <<<128, 256>>>(W1);
    fused_w1_out_kernel<<<512, 256>>>(W1, Wo, out_w1, out);
    fused_w0_kernel    <<<256, 256>>>(W0, out_w0);
}

// round 17
// speedup vs baseline: 1.2615x; 1.0486x over previous
#include <cuda_runtime.h>
#include <math.h>

#define B    16
#define IN   1024
#define HH   1024
#define DKK  1024
#define D1   4096
#define LRC  0.01f
#define NCH  64
#define CI   16

// ---------------- scratch (allocation-free) ----------------
__device__ __align__(16) float g_K  [B * DKK];          // b-major
__device__ __align__(16) float g_V  [B * HH];           // b-major
__device__ __align__(16) float g_G  [B * D1];           // b-major
__device__ __align__(16) float g_Gp [B * D1];           // b-major
__device__ __align__(16) float g_Hd [B * HH];           // b-major
__device__ __align__(16) float g_dHt[HH * B];           // i-major
__device__ __align__(16) float g_part[NCH * B * D1];    // [c][b][j], 16 MB

__device__ __forceinline__ float warp_sum(float v) {
    v += __shfl_xor_sync(0xffffffffu, v, 16);
    v += __shfl_xor_sync(0xffffffffu, v, 8);
    v += __shfl_xor_sync(0xffffffffu, v, 4);
    v += __shfl_xor_sync(0xffffffffu, v, 2);
    v += __shfl_xor_sync(0xffffffffu, v, 1);
    return v;
}
__device__ __forceinline__ float dot4(float4 a, float4 b) {
    return a.x * b.x + a.y * b.y + a.z * b.z + a.w * b.w;
}

// ---------------- proj: split-4, 2 row-groups/block, 256 blocks ----------------
__global__ void __launch_bounds__(256, 2)
proj_kernel(const float* __restrict__ X,
            const float* __restrict__ Wk,
            const float* __restrict__ Wv) {
    __shared__ float sm[2][4][64];
    int w = threadIdx.x >> 5, lane = threadIdx.x & 31;
    int rgl = w >> 2, q = w & 3;
    int rg = blockIdx.x * 2 + rgl;            // 0..511
    const float* Wb = (rg >> 8) ? Wv : Wk;
    int row0 = (rg * 4) & 1023;
    int ibase = q * 256;
    const float* wp = Wb + (size_t)row0 * IN + ibase;
    const float* xp = X + ibase;

    float acc[4][16];
#pragma unroll
    for (int r = 0; r < 4; r++)
#pragma unroll
        for (int b = 0; b < 16; b++) acc[r][b] = 0.f;

#pragma unroll
    for (int it = 0; it < 2; it++) {
        int i = it * 128 + lane * 4;
        float4 wv[4];
#pragma unroll
        for (int r = 0; r < 4; r++) wv[r] = __ldg((const float4*)(wp + r * IN + i));
#pragma unroll
        for (int b = 0; b < 16; b++) {
            float4 x4 = __ldg((const float4*)(xp + b * IN + i));
#pragma unroll
            for (int r = 0; r < 4; r++) acc[r][b] += dot4(wv[r], x4);
        }
    }
#pragma unroll
    for (int r = 0; r < 4; r++)
#pragma unroll
        for (int b = 0; b < 16; b++) acc[r][b] = warp_sum(acc[r][b]);
    if (lane == 0) {
#pragma unroll
        for (int r = 0; r < 4; r++)
#pragma unroll
            for (int b = 0; b < 16; b++) sm[rgl][q][r * 16 + b] = acc[r][b];
    }
    __syncthreads();
    if (threadIdx.x < 128) {
        int t = threadIdx.x;
        int rg2 = t >> 6, r = (t >> 4) & 3, b = t & 15;
        float v = sm[rg2][0][r * 16 + b] + sm[rg2][1][r * 16 + b]
                + sm[rg2][2][r * 16 + b] + sm[rg2][3][r * 16 + b];
        int row = (blockIdx.x * 2 + rg2) * 4 + r;
        float* o = (row >> 10) ? g_V : g_K;
        o[b * 1024 + (row & 1023)] = v;
    }
}

// ---------------- zgelu: Z = K @ W0^T ; G, Gp (unchanged, 256 blocks) ----------------
__global__ void __launch_bounds__(256, 2)
zgelu_kernel(const float* __restrict__ W0) {
    __shared__ float sm[4][2][64];
    int w = threadIdx.x >> 5, lane = threadIdx.x & 31;
    int rgl = w >> 1, half = w & 1;
    int rg = blockIdx.x * 4 + rgl;            // 0..1023
    int j0 = rg * 4;
    int ibase = half * 512;
    const float* wp = W0 + (size_t)j0 * DKK + ibase;

    float acc[4][16];
#pragma unroll
    for (int r = 0; r < 4; r++)
#pragma unroll
        for (int b = 0; b < 16; b++) acc[r][b] = 0.f;

#pragma unroll
    for (int it = 0; it < 4; it++) {
        int i = it * 128 + lane * 4;
        float4 wv[4];
#pragma unroll
        for (int r = 0; r < 4; r++) wv[r] = __ldg((const float4*)(wp + r * DKK + i));
#pragma unroll
        for (int b = 0; b < 16; b++) {
            float4 k4 = *(const float4*)(g_K + b * DKK + ibase + i);
#pragma unroll
            for (int r = 0; r < 4; r++) acc[r][b] += dot4(wv[r], k4);
        }
    }
#pragma unroll
    for (int r = 0; r < 4; r++)
#pragma unroll
        for (int b = 0; b < 16; b++) acc[r][b] = warp_sum(acc[r][b]);
    if (lane == 0) {
#pragma unroll
        for (int r = 0; r < 4; r++)
#pragma unroll
            for (int b = 0; b < 16; b++) sm[rgl][half][r * 16 + b] = acc[r][b];
    }
    __syncthreads();
    {
        int t = threadIdx.x;
        int rg2 = t >> 6, r = (t >> 4) & 3, b = t & 15;
        float z = sm[rg2][0][r * 16 + b] + sm[rg2][1][r * 16 + b];
        int j = (blockIdx.x * 4 + rg2) * 4 + r;
        float c  = 0.5f * (1.f + erff(z * 0.70710678118654752f));
        float g  = z * c;
        float gp = c + z * 0.39894228040143268f * expf(-0.5f * z * z);
        g_G [b * D1 + j] = g;
        g_Gp[b * D1 + j] = gp;
    }
}

// ---------------- hdh: split-8, 1 row-group/block, 256 blocks ----------------
__global__ void __launch_bounds__(256, 2)
hdh_kernel(const float* __restrict__ W1) {
    __shared__ float sm[8][64];
    int w = threadIdx.x >> 5, lane = threadIdx.x & 31;
    int s = w;                                // 0..7
    int i0 = blockIdx.x * 4;                  // 4 rows per block
    int jbase = s * 512;
    const float* wp = W1 + (size_t)i0 * D1 + jbase;

    float acc[4][16];
#pragma unroll
    for (int r = 0; r < 4; r++)
#pragma unroll
        for (int b = 0; b < 16; b++) acc[r][b] = 0.f;

#pragma unroll
    for (int it = 0; it < 4; it++) {
        int j = it * 128 + lane * 4;
        float4 wv[4];
#pragma unroll
        for (int r = 0; r < 4; r++) wv[r] = __ldg((const float4*)(wp + r * D1 + j));
#pragma unroll
        for (int b = 0; b < 16; b++) {
            float4 g4 = *(const float4*)(g_G + b * D1 + jbase + j);
#pragma unroll
            for (int r = 0; r < 4; r++) acc[r][b] += dot4(wv[r], g4);
        }
    }
#pragma unroll
    for (int r = 0; r < 4; r++)
#pragma unroll
        for (int b = 0; b < 16; b++) acc[r][b] = warp_sum(acc[r][b]);
    if (lane == 0) {
#pragma unroll
        for (int r = 0; r < 4; r++)
#pragma unroll
            for (int b = 0; b < 16; b++) sm[s][r * 16 + b] = acc[r][b];
    }
    __syncthreads();
    if (threadIdx.x < 64) {
        int t = threadIdx.x;
        int r = t >> 4, b = t & 15;
        float h = 0.f;
#pragma unroll
        for (int ss = 0; ss < 8; ss++) h += sm[ss][r * 16 + b];
        int i = blockIdx.x * 4 + r;
        g_Hd [b * HH + i] = h;
        g_dHt[i * B + b]  = (h - g_V[b * HH + i]) * (1.0f / (float)HH);
    }
}

// ---------------- MEGA: W1 update + dG partials (blocks 0..255) | output GEMV (256..511) ----------------
__global__ void fused_w1_out_kernel(const float* __restrict__ W1,
                                    const float* __restrict__ Wo,
                                    float* __restrict__ out_w1,
                                    float* __restrict__ out) {
    int tid = threadIdx.x;
    if (blockIdx.x < 256) {
        __shared__ float sdh[CI * B];
        int c  = blockIdx.x >> 2;           // 0..63
        int jt = blockIdx.x & 3;
        int i0 = c * CI;
        int j  = jt * 1024 + tid * 4;

        sdh[tid] = g_dHt[i0 * B + tid];     // 16 rows x 16 b
        __syncthreads();

#pragma unroll
        for (int half = 0; half < 2; half++) {
            float4 gg[8], acc[8];
#pragma unroll
            for (int bb = 0; bb < 8; bb++) {
                gg[bb]  = *(const float4*)(g_G + (half * 8 + bb) * D1 + j);
                acc[bb] = make_float4(0.f, 0.f, 0.f, 0.f);
            }
#pragma unroll 4
            for (int r = 0; r < CI; r++) {
                int i = i0 + r;
                float4 w4 = __ldg((const float4*)(W1 + (size_t)i * D1 + j));
                float* dst = out_w1 + (size_t)i * D1 + j;
#pragma unroll
                for (int bb = 0; bb < 8; bb++) {
                    int b = half * 8 + bb;
                    float dh = sdh[r * B + b];
                    acc[bb].x += dh * w4.x;
                    acc[bb].y += dh * w4.y;
                    acc[bb].z += dh * w4.z;
                    acc[bb].w += dh * w4.w;
                    float t = LRC * dh;
                    float4 o;
                    o.x = w4.x - t * gg[bb].x;
                    o.y = w4.y - t * gg[bb].y;
                    o.z = w4.z - t * gg[bb].z;
                    o.w = w4.w - t * gg[bb].w;
                    __stcs((float4*)(dst + (size_t)b * HH * D1), o);
                }
            }
#pragma unroll
            for (int bb = 0; bb < 8; bb++)
                *(float4*)(g_part + ((size_t)c * B + half * 8 + bb) * D1 + j) = acc[bb];
        }
    } else {
        // output = Hd @ Wo^T (split-2, 4 rows/block)
        __shared__ float sm[4][2][B];
        int bx2  = blockIdx.x - 256;
        int w    = tid >> 5;
        int lane = tid & 31;
        int r = w >> 1;
        int s = w & 1;
        int n = bx2 * 4 + r;
        const float* wrow = Wo + (size_t)n * HH + s * 512;

        float acc[B];
#pragma unroll
        for (int b = 0; b < B; b++) acc[b] = 0.f;

#pragma unroll 4
        for (int it = 0; it < 4; it++) {
            int h0 = it * 128 + lane * 4;
            float4 w4 = __ldg((const float4*)(wrow + h0));
#pragma unroll
            for (int b = 0; b < B; b++) {
                float4 h4 = *(const float4*)(g_Hd + b * HH + s * 512 + h0);
                acc[b] += dot4(w4, h4);
            }
        }
#pragma unroll
        for (int b = 0; b < B; b++) acc[b] = warp_sum(acc[b]);
        if (lane == 0) {
#pragma unroll
            for (int b = 0; b < B; b++) sm[r][s][b] = acc[b];
        }
        __syncthreads();
        if (tid < 64) {
            int rr = tid >> 4;
            int b  = tid & 15;
            int nn = bx2 * 4 + rr;
            out[b * IN + nn] = sm[rr][0][b] + sm[rr][1][b];
        }
    }
}

// ---------------- fused: dZ reduce + W0 update. 256 blocks x 256 thr, 16 d1-rows each ----------------
__global__ void fused_w0_kernel(const float* __restrict__ W0,
                                float* __restrict__ out_w0) {
    __shared__ float sdz[256];                 // [b][r]
    int tid  = threadIdx.x;
    int d1_0 = blockIdx.x * 16;

    {
        int b = tid >> 4, d = tid & 15;
        const float* pp = g_part + (size_t)b * D1 + d1_0 + d;
        float s = 0.f;
#pragma unroll 16
        for (int c = 0; c < NCH; c++)
            s += pp[(size_t)c * (B * D1)];
        sdz[b * 16 + d] = LRC * s * g_Gp[b * D1 + d1_0 + d];
    }
    __syncthreads();

    int col = tid * 4;
    float4 kk[16];
#pragma unroll
    for (int b = 0; b < 16; b++) kk[b] = *(const float4*)(g_K + b * DKK + col);

#pragma unroll 2
    for (int r = 0; r < 16; r++) {
        int d1 = d1_0 + r;
        float4 w4 = __ldg((const float4*)(W0 + (size_t)d1 * DKK + col));
#pragma unroll
        for (int b = 0; b < 16; b++) {
            float s = sdz[b * 16 + r];
            float4 o;
            o.x = w4.x - s * kk[b].x;
            o.y = w4.y - s * kk[b].y;
            o.z = w4.z - s * kk[b].z;
            o.w = w4.w - s * kk[b].w;
            __stcs((float4*)(out_w0 + ((size_t)b * D1 + d1) * DKK + col), o);
        }
    }
}

extern "C" void kernel_launch(void* const* d_in, const int* in_sizes, int n_in,
                              void* d_out, int out_size) {
    const float* x  = (const float*)d_in[0];
    const float* Wk = (const float*)d_in[1];
    const float* Wv = (const float*)d_in[2];
    const float* Wo = (const float*)d_in[3];
    const float* W0 = (const float*)d_in[4];
    const float* W1 = (const float*)d_in[5];

    float* out    = (float*)d_out;
    float* out_w0 = out + (size_t)B * IN;
    float* out_w1 = out_w0 + (size_t)B * D1 * DKK;

    proj_kernel        <<<256, 256>>>(x, Wk, Wv);
    zgelu_kernel       <<<256, 256>>>(W0);
    hdh_kernel         <<<256, 256>>>(W1);
    fused_w1_out_kernel<<<512, 256>>>(W1, Wo, out_w1, out);
    fused_w0_kernel    <<<256, 256>>>(W0, out_w0);
}